// round 13
// baseline (speedup 1.0000x reference)
#include <cuda_runtime.h>
#include <cuda_fp16.h>
#include <math.h>
#include <stdint.h>

// ============================ helpers ============================
__device__ __forceinline__ uint32_t smem_to_u32(const void* p) {
    uint32_t a;
    asm("{ .reg .u64 t; cvta.to.shared.u64 t, %1; cvt.u32.u64 %0, t; }"
        : "=r"(a) : "l"(p));
    return a;
}
__device__ __forceinline__ void cp_async16(uint32_t smem, const void* g, uint32_t sz) {
    asm volatile("cp.async.cg.shared.global [%0], [%1], 16, %2;"
                 :: "r"(smem), "l"(g), "r"(sz) : "memory");
}
#define CP_COMMIT() asm volatile("cp.async.commit_group;" ::: "memory")
#define CP_WAIT1() asm volatile("cp.async.wait_group 1;" ::: "memory")
#define CP_WAIT0() asm volatile("cp.async.wait_group 0;" ::: "memory")
#define LDSM4(r0, r1, r2, r3, addr) \
    asm volatile("ldmatrix.sync.aligned.m8n8.x4.shared.b16 {%0,%1,%2,%3}, [%4];" \
                 : "=r"(r0), "=r"(r1), "=r"(r2), "=r"(r3) : "r"(addr))
__device__ __forceinline__ void mma16816(float* c, const uint32_t* a, uint32_t b0,
                                         uint32_t b1) {
    asm volatile(
        "mma.sync.aligned.m16n8k16.row.col.f32.f16.f16.f32 "
        "{%0,%1,%2,%3}, {%4,%5,%6,%7}, {%8,%9}, {%0,%1,%2,%3};"
        : "+f"(c[0]), "+f"(c[1]), "+f"(c[2]), "+f"(c[3])
        : "r"(a[0]), "r"(a[1]), "r"(a[2]), "r"(a[3]), "r"(b0), "r"(b1));
}
#define SWZ(x) ((x) ^ (((x) >> 3) & 0x70))

// ============================ scratch (device globals) ============================
__device__ __align__(16) __half g_a1h[12845056];   // conv2 A limbs [pos][ch]
__device__ __align__(16) __half g_a1l[12845056];
__device__ __align__(16) __half g_w2h[1048576];    // conv2 B limbs [n][4096]
__device__ __align__(16) __half g_w2l[1048576];
__device__ __align__(16) __half g_dh[6422528];     // deconv1 A (hi only) [pos][ch]
__device__ __align__(16) __half g_w1h[1638400];    // deconv1 parity weights (hi only)
__device__ float g_w2c[9216];        // deconv2 parity-combined weights [4][9][256]
__device__ float g_h2[3211264];      // pooled conv2 out (atomicMax target)
__device__ float g_encp[802816];     // encoder split-K partials (49 chunks)
__device__ float g_z[32768];         // rows 0..255 z_e, 256..511 z_q
__device__ __align__(16) __half g_g1h[25690112];   // deconv1 out (fp16)

// ============== fused prep: zero | conv1pool | wsplit2 | wcomb | wcomb2 ===========
// block ranges: [0,3136) zero, [3136,6720) conv1pool, [6720,7744) wsplit2,
//               [7744,14144) wcomb, [14144,14180) wcomb2
__global__ __launch_bounds__(256) void k_prep(const float* __restrict__ x,
                                              const float* __restrict__ w1,
                                              const float* __restrict__ b1,
                                              const float* __restrict__ w2,
                                              const float* __restrict__ d1w,
                                              const float* __restrict__ d2w) {
    __shared__ __align__(16) char sm[4352];
    const int b = blockIdx.x;
    const int t = threadIdx.x;
    if (b < 3136) {
        int i = b * 256 + t;
        if (i < 802816) *(((uint4*)g_h2) + i) = make_uint4(0u, 0u, 0u, 0u);
    } else if (b < 6720) {
        int bb = b - 3136;
        int py = bb % 14;
        int img = bb / 14;
        int c = t;
        float(*xs)[32] = (float(*)[32])sm;
        for (int e = t; e < 5 * 32; e += 256) {
            int r = e / 32, cc = e % 32;
            int iy = 2 * py - 1 + r;
            int ix = cc - 1;
            float v = 0.f;
            if (iy >= 0 && iy < 28 && ix >= 0 && ix < 28)
                v = x[(img * 28 + iy) * 28 + ix];
            xs[r][cc] = v;
        }
        float w[16];
#pragma unroll
        for (int i = 0; i < 16; i++) w[i] = w1[i * 256 + c];
        float bias = b1[c];
        __syncthreads();
        for (int px = 0; px < 14; px++) {
            float mv = -1e30f;
#pragma unroll
            for (int dy = 0; dy < 2; dy++)
#pragma unroll
                for (int dx = 0; dx < 2; dx++) {
                    float v = bias;
#pragma unroll
                    for (int ky = 0; ky < 4; ky++)
#pragma unroll
                        for (int kx = 0; kx < 4; kx++)
                            v += xs[dy + ky][2 * px + dx + kx] * w[ky * 4 + kx];
                    mv = fmaxf(mv, v);
                }
            float val = fmaxf(mv, 0.f);
            int idx = ((img * 14 + py) * 14 + px) * 256 + c;
            __half h = __float2half(val);
            g_a1h[idx] = h;
            g_a1l[idx] = __float2half(val - __half2float(h));
        }
    } else if (b < 7744) {
        int i = b - 6720;
        int k0 = (i & 127) * 32, n0 = (i >> 7) * 32;
        float(*tile)[33] = (float(*)[33])sm;
        int tx = t & 31, ty = t >> 5;
#pragma unroll
        for (int r = 0; r < 32; r += 8)
            tile[ty + r][tx] = w2[(k0 + ty + r) * 256 + n0 + tx];
        __syncthreads();
#pragma unroll
        for (int r = 0; r < 32; r += 8) {
            float v = tile[tx][ty + r];
            int n = n0 + ty + r;
            int idx = n * 4096 + k0 + tx;
            __half h = __float2half(v);
            g_w2h[idx] = h;
            g_w2l[idx] = __float2half(v - __half2float(h));
        }
    } else if (b < 14144) {
        int idx = (b - 7744) * 256 + t;
        int c, base;
        if (idx < 589824) { c = 0; base = 0; }
        else if (idx < 983040) { c = 1; base = 589824; }
        else if (idx < 1376256) { c = 2; base = 983040; }
        else { c = 3; base = 1376256; }
        int py = c >> 1, px = c & 1;
        int TX = 3 - px;
        int Kc = (3 - py) * TX * 256;
        int rem = idx - base;
        int n = rem / Kc;
        int k = rem % Kc;
        int tap = k >> 8, cin = k & 255;
        int ty = tap / TX, tx = tap % TX;
        int kys, kyn, kxs, kxn;
        if (py == 0) { kys = (ty == 0) ? 0 : (ty == 1) ? 1 : 3; kyn = (ty == 1) ? 2 : 1; }
        else { kys = ty * 2; kyn = 2; }
        if (px == 0) { kxs = (tx == 0) ? 0 : (tx == 1) ? 1 : 3; kxn = (tx == 1) ? 2 : 1; }
        else { kxs = tx * 2; kxn = 2; }
        float s = 0.f;
        for (int a = 0; a < kyn; a++)
            for (int bb = 0; bb < kxn; bb++)
                s += d1w[(((kys + a) * 4 + kxs + bb) * 256 + cin) * 256 + n];
        g_w1h[idx] = __float2half(s);
    } else {
        int i = (b - 14144) * 256 + t;
        if (i >= 9216) return;
        int cls = i / 2304;
        int rem = i % 2304;
        int tap = rem >> 8;
        int cin = rem & 255;
        int py = cls >> 1, px = cls & 1;
        int TX = 3 - px, TY = 3 - py;
        if (tap >= TY * TX) { g_w2c[i] = 0.f; return; }
        int ty = tap / TX, tx = tap % TX;
        int kys, kyn, kxs, kxn;
        if (py == 0) { kys = (ty == 0) ? 0 : (ty == 1) ? 1 : 3; kyn = (ty == 1) ? 2 : 1; }
        else { kys = ty * 2; kyn = 2; }
        if (px == 0) { kxs = (tx == 0) ? 0 : (tx == 1) ? 1 : 3; kxn = (tx == 1) ? 2 : 1; }
        else { kxs = tx * 2; kxn = 2; }
        float s = 0.f;
        for (int a = 0; a < kyn; a++)
            for (int bb = 0; bb < kxn; bb++)
                s += d2w[((kys + a) * 4 + kxs + bb) * 256 + cin];
        g_w2c[i] = s;
    }
}

// ====== encoder HMMA conv2 (M=128,N=128,K=4096), 512 threads, 16 warps 4x4 ========
// fp16 2-limb, 3 passes. K=64 stages, 3-stage pipeline, single sync/stage.
__global__ __launch_bounds__(512, 1) void k_hmma_enc(
    const __half* __restrict__ a0p, const __half* __restrict__ a1p,
    const __half* __restrict__ b0p, const __half* __restrict__ b1p,
    const float* __restrict__ bias, float* __restrict__ outpool) {
    constexpr int STAGE = 65536;
    extern __shared__ __align__(1024) char smem[];
    const uint32_t sb = smem_to_u32(smem);
    const int t = threadIdx.x;
    const int wid = t >> 5;
    const int lane = t & 31;
    const int wr = wid & 3;    // M quarter (32 rows)
    const int wc = wid >> 2;   // N quarter (32 cols)
    const int m0 = blockIdx.x * 128;
    const int n0 = blockIdx.y * 128;

    // loader: rows rr + 64*j (j=0,1), seg = t&7
    const int rr = t >> 3;
    const int seg = t & 7;
    int imgA[2], oyA[2], oxA[2];
    uint32_t stsO[2];
#pragma unroll
    for (int j = 0; j < 2; j++) {
        int m = m0 + rr + 64 * j;
        imgA[j] = m / 196;
        int p = m % 196;
        oyA[j] = p / 14;
        oxA[j] = p % 14;
        stsO[j] = SWZ((uint32_t)((rr + 64 * j) * 128 + seg * 16));
    }

    float acc[2][4][4];
#pragma unroll
    for (int i = 0; i < 2; i++)
#pragma unroll
        for (int j = 0; j < 4; j++)
#pragma unroll
            for (int q = 0; q < 4; q++) acc[i][j][q] = 0.f;

    const int arow = wr * 32 + (lane & 15);
    const uint32_t acolbase = (uint32_t)((lane >> 4) * 16);
    const int brow = wc * 32 + (lane & 7) + (lane >> 4) * 8;
    const uint32_t bcolbase = (uint32_t)(((lane >> 3) & 1) * 16);

    auto issue = [&](int s, int buf) {
        const int tap = s >> 2;
        const int ky = tap >> 2, kx = tap & 3;
        const int ch0 = (s & 3) * 64;
        const uint32_t sbuf = sb + (uint32_t)buf * STAGE;
#pragma unroll
        for (int j = 0; j < 2; j++) {
            int iy = oyA[j] - 1 + ky;
            int ix = oxA[j] - 1 + kx;
            bool v = ((unsigned)iy < 14u) && ((unsigned)ix < 14u);
            int pos = imgA[j] * 196 + iy * 14 + ix;
            int aoff = v ? (pos * 256 + ch0 + seg * 8) : 0;
            uint32_t sz = v ? 16u : 0u;
            cp_async16(sbuf + stsO[j], a0p + aoff, sz);
            cp_async16(sbuf + 16384 + stsO[j], a1p + aoff, sz);
            size_t boff = (size_t)(n0 + rr + 64 * j) * 4096 + s * 64 + seg * 8;
            cp_async16(sbuf + 32768 + stsO[j], b0p + boff, 16u);
            cp_async16(sbuf + 49152 + stsO[j], b1p + boff, 16u);
        }
    };

    issue(0, 0);
    CP_COMMIT();
    issue(1, 1);
    CP_COMMIT();

    int buf = 0;
    for (int s = 0; s < 64; s++) {
        if (s + 1 < 64) CP_WAIT1(); else CP_WAIT0();
        __syncthreads();
        if (s + 2 < 64) {
            int nb = buf + 2;
            if (nb >= 3) nb -= 3;
            issue(s + 2, nb);
            CP_COMMIT();
        }
        const uint32_t abase = sb + (uint32_t)buf * STAGE;
        const uint32_t bbase = abase + 32768;
#pragma unroll
        for (int kk = 0; kk < 4; kk++) {
            uint32_t af[2][2][4];
            uint32_t bf[2][2][4];
            const uint32_t acol = acolbase + kk * 32;
#pragma unroll
            for (int la = 0; la < 2; la++)
#pragma unroll
                for (int mt = 0; mt < 2; mt++) {
                    int row = arow + mt * 16;
                    LDSM4(af[la][mt][0], af[la][mt][1], af[la][mt][2], af[la][mt][3],
                          abase + la * 16384 + row * 128 + (acol ^ ((row & 7) * 16)));
                }
            const uint32_t bcol = bcolbase + kk * 32;
#pragma unroll
            for (int lb = 0; lb < 2; lb++)
#pragma unroll
                for (int nt2 = 0; nt2 < 2; nt2++) {
                    int row = brow + nt2 * 16;
                    LDSM4(bf[lb][nt2][0], bf[lb][nt2][1], bf[lb][nt2][2],
                          bf[lb][nt2][3],
                          bbase + lb * 16384 + row * 128 + (bcol ^ ((row & 7) * 16)));
                }
#pragma unroll
            for (int p = 0; p < 3; p++) {
                const int la = (p == 2) ? 1 : 0;
                const int lb = (p == 1) ? 1 : 0;
#pragma unroll
                for (int mt = 0; mt < 2; mt++)
#pragma unroll
                    for (int nt = 0; nt < 4; nt++)
                        mma16816(acc[mt][nt], af[la][mt],
                                 bf[lb][nt >> 1][(nt & 1) * 2],
                                 bf[lb][nt >> 1][(nt & 1) * 2 + 1]);
            }
        }
        if (++buf == 3) buf = 0;
    }

    // epilogue: bias + ReLU + fused 2x2 maxpool via atomicMax (values >= 0)
    unsigned* outp = (unsigned*)outpool;
#pragma unroll
    for (int mt = 0; mt < 2; mt++) {
#pragma unroll
        for (int nt = 0; nt < 4; nt++) {
            int col = n0 + wc * 32 + nt * 8 + (lane & 3) * 2;
            float b0v = bias[col], b1v = bias[col + 1];
#pragma unroll
            for (int h8 = 0; h8 < 2; h8++) {
                int m = m0 + wr * 32 + mt * 16 + (lane >> 2) + h8 * 8;
                int img = m / 196;
                int p = m % 196;
                int py = (p / 14) >> 1;
                int px = (p % 14) >> 1;
                size_t base = (size_t)((img * 7 + py) * 7 + px) * 256 + col;
                float v0 = fmaxf(acc[mt][nt][h8 * 2] + b0v, 0.f);
                float v1 = fmaxf(acc[mt][nt][h8 * 2 + 1] + b1v, 0.f);
                atomicMax(outp + base, __float_as_uint(v0));
                atomicMax(outp + base + 1, __float_as_uint(v1));
            }
        }
    }
}

// ====== decoder HMMA: parity classes, single-limb, 512 threads, fp16 out ==========
__global__ __launch_bounds__(512, 1) void k_hmma_dec(
    const __half* __restrict__ a0p, const __half* __restrict__ b0p,
    const float* __restrict__ bias, __half* __restrict__ out) {
    constexpr int STAGE = 32768;
    extern __shared__ __align__(1024) char smem[];
    const uint32_t sb = smem_to_u32(smem);
    const int t = threadIdx.x;
    const int wid = t >> 5;
    const int lane = t & 31;
    const int wr = wid & 3;
    const int wc = wid >> 2;
    const int m0 = blockIdx.x * 128;
    const int n0 = blockIdx.y * 128;
    const int cls = blockIdx.z;
    const int py = cls >> 1, px = cls & 1;
    const int TX = 3 - px;
    const int TY = 3 - py;
    const int nst = TY * TX * 4;
    const int Kc = TY * TX * 256;
    const int woff = (cls == 0) ? 0 : (cls == 1) ? 589824 : (cls == 2) ? 983040
                                                                       : 1376256;

    const int rr = t >> 3;
    const int seg = t & 7;
    int imgA[2], syA[2], sxA[2];
    uint32_t stsO[2];
#pragma unroll
    for (int j = 0; j < 2; j++) {
        int m = m0 + rr + 64 * j;
        imgA[j] = m / 49;
        int p = m % 49;
        syA[j] = p / 7;
        sxA[j] = p % 7;
        stsO[j] = SWZ((uint32_t)((rr + 64 * j) * 128 + seg * 16));
    }

    float acc[2][4][4];
#pragma unroll
    for (int i = 0; i < 2; i++)
#pragma unroll
        for (int j = 0; j < 4; j++)
#pragma unroll
            for (int q = 0; q < 4; q++) acc[i][j][q] = 0.f;

    const int arow = wr * 32 + (lane & 15);
    const uint32_t acolbase = (uint32_t)((lane >> 4) * 16);
    const int brow = wc * 32 + (lane & 7) + (lane >> 4) * 8;
    const uint32_t bcolbase = (uint32_t)(((lane >> 3) & 1) * 16);

    auto issue = [&](int s, int buf) {
        const int tap = s >> 2;
        const int ch0 = (s & 3) * 64;
        const int ty = tap / TX, tx = tap % TX;
        const uint32_t sbuf = sb + (uint32_t)buf * STAGE;
#pragma unroll
        for (int j = 0; j < 2; j++) {
            int iy = syA[j] + ty + (py - 1);
            int ix = sxA[j] + tx + (px - 1);
            bool v = ((unsigned)iy < 7u) && ((unsigned)ix < 7u);
            int pos = imgA[j] * 49 + iy * 7 + ix;
            int aoff = v ? (pos * 256 + ch0 + seg * 8) : 0;
            uint32_t sz = v ? 16u : 0u;
            cp_async16(sbuf + stsO[j], a0p + aoff, sz);
            size_t boff = (size_t)woff + (size_t)(n0 + rr + 64 * j) * Kc + s * 64 +
                          seg * 8;
            cp_async16(sbuf + 16384 + stsO[j], b0p + boff, 16u);
        }
    };

    issue(0, 0);
    CP_COMMIT();
    issue(1, 1);
    CP_COMMIT();

    int buf = 0;
    for (int s = 0; s < nst; s++) {
        if (s + 1 < nst) CP_WAIT1(); else CP_WAIT0();
        __syncthreads();
        if (s + 2 < nst) {
            int nb = buf + 2;
            if (nb >= 3) nb -= 3;
            issue(s + 2, nb);
            CP_COMMIT();
        }
        const uint32_t abase = sb + (uint32_t)buf * STAGE;
        const uint32_t bbase = abase + 16384;
#pragma unroll
        for (int kk = 0; kk < 4; kk++) {
            uint32_t af[2][4];
            uint32_t bf[2][4];
            const uint32_t acol = acolbase + kk * 32;
#pragma unroll
            for (int mt = 0; mt < 2; mt++) {
                int row = arow + mt * 16;
                LDSM4(af[mt][0], af[mt][1], af[mt][2], af[mt][3],
                      abase + row * 128 + (acol ^ ((row & 7) * 16)));
            }
            const uint32_t bcol = bcolbase + kk * 32;
#pragma unroll
            for (int nt2 = 0; nt2 < 2; nt2++) {
                int row = brow + nt2 * 16;
                LDSM4(bf[nt2][0], bf[nt2][1], bf[nt2][2], bf[nt2][3],
                      bbase + row * 128 + (bcol ^ ((row & 7) * 16)));
            }
#pragma unroll
            for (int mt = 0; mt < 2; mt++)
#pragma unroll
                for (int nt = 0; nt < 4; nt++)
                    mma16816(acc[mt][nt], af[mt], bf[nt >> 1][(nt & 1) * 2],
                             bf[nt >> 1][(nt & 1) * 2 + 1]);
        }
        if (++buf == 3) buf = 0;
    }

    // epilogue: scatter rows back to the 14x14 grid, bias + ReLU, fp16 store
#pragma unroll
    for (int mt = 0; mt < 2; mt++) {
#pragma unroll
        for (int nt = 0; nt < 4; nt++) {
            int col = n0 + wc * 32 + nt * 8 + (lane & 3) * 2;
            float b0v = bias[col], b1v = bias[col + 1];
#pragma unroll
            for (int half8 = 0; half8 < 2; half8++) {
                int m = m0 + wr * 32 + mt * 16 + (lane >> 2) + half8 * 8;
                int img = m / 49;
                int p = m % 49;
                int oy = 2 * (p / 7) + py;
                int ox = 2 * (p % 7) + px;
                float v0 = fmaxf(acc[mt][nt][half8 * 2] + b0v, 0.f);
                float v1 = fmaxf(acc[mt][nt][half8 * 2 + 1] + b1v, 0.f);
                __half2 hv = __floats2half2_rn(v0, v1);
                *(__half2*)(out + (size_t)((img * 14 + oy) * 14 + ox) * 256 + col) = hv;
            }
        }
    }
}

// ---------------- K4: encoder FC split-K (49 chunks of K=256) ----------------
__global__ __launch_bounds__(256) void k_enc_part(const float* __restrict__ h2,
                                                  const float* __restrict__ ew) {
    int kc = blockIdx.x;
    int b0 = blockIdx.y * 64;
    __shared__ float As[8][64];
    __shared__ float Bs[8][64];
    int t = threadIdx.x;
    int abb = t >> 2, akk = (t & 3) * 2;
    int bkk = t >> 5, bll = (t & 31) * 2;
    int tr = t >> 4, tc = t & 15;
    float acc[4][4] = {};
    int kbase = kc * 256;
    for (int ks = 0; ks < 256; ks += 8) {
        int k0 = kbase + ks;
        float2 av = *(const float2*)&h2[(b0 + abb) * 12544 + k0 + akk];
        float2 bv = *(const float2*)&ew[(k0 + bkk) * 64 + bll];
        __syncthreads();
        As[akk][abb] = av.x;
        As[akk + 1][abb] = av.y;
        *(float2*)&Bs[bkk][bll] = bv;
        __syncthreads();
#pragma unroll
        for (int kk = 0; kk < 8; kk++) {
            float a[4], b[4];
#pragma unroll
            for (int i = 0; i < 4; i++) a[i] = As[kk][tr * 4 + i];
#pragma unroll
            for (int j = 0; j < 4; j++) b[j] = Bs[kk][tc * 4 + j];
#pragma unroll
            for (int i = 0; i < 4; i++)
#pragma unroll
                for (int j = 0; j < 4; j++) acc[i][j] += a[i] * b[j];
        }
    }
#pragma unroll
    for (int i = 0; i < 4; i++)
#pragma unroll
        for (int j = 0; j < 4; j++)
            g_encp[(kc * 256 + b0 + tr * 4 + i) * 64 + tc * 4 + j] = acc[i][j];
}

// ---------------- K5: fused reduce + argmin + z_q gather (grid 256) ----------------
__global__ __launch_bounds__(256) void k_redargmin(const float* __restrict__ emb,
                                                   const float* __restrict__ eb) {
    int b = blockIdx.x;
    __shared__ float zb[64];
    __shared__ float ds[256];
    __shared__ int ki[256];
    int t = threadIdx.x;
    if (t < 64) {
        float s = eb[t];
        for (int kc = 0; kc < 49; kc++) s += g_encp[kc * 16384 + b * 64 + t];
        zb[t] = s;
        g_z[b * 64 + t] = s;
    }
    __syncthreads();
    float d = 0.f;
    const float* e = emb + t * 64;
#pragma unroll 8
    for (int j = 0; j < 64; j++) {
        float df = zb[j] - e[j];
        d += df * df;
    }
    ds[t] = d;
    ki[t] = t;
    __syncthreads();
    for (int s = 128; s > 0; s >>= 1) {
        if (t < s) {
            float d2 = ds[t + s];
            int k2 = ki[t + s];
            if (d2 < ds[t] || (d2 == ds[t] && k2 < ki[t])) { ds[t] = d2; ki[t] = k2; }
        }
        __syncthreads();
    }
    int kb = ki[0];
    if (t < 64) g_z[(256 + b) * 64 + t] = emb[kb * 64 + t];
}

// ---------------- K6: decoder FC -> fp16 hi plane only ----------------
__global__ __launch_bounds__(256) void k_decfc(const float* __restrict__ dw,
                                               const float* __restrict__ db) {
    int n0 = blockIdx.x * 128;
    int m0 = blockIdx.y * 64;
    __shared__ float Zs[64][64];
    __shared__ float Bs[32][128];
    int t = threadIdx.x;
    {
        int rr = t >> 2, kk0 = (t & 3) * 16;
        const float* zp = &g_z[(m0 + rr) * 64 + kk0];
#pragma unroll
        for (int q = 0; q < 4; q++) {
            float4 v = *(const float4*)(zp + q * 4);
            Zs[kk0 + q * 4 + 0][rr] = v.x; Zs[kk0 + q * 4 + 1][rr] = v.y;
            Zs[kk0 + q * 4 + 2][rr] = v.z; Zs[kk0 + q * 4 + 3][rr] = v.w;
        }
    }
    int tr = t >> 5;
    int tc = t & 31;
    float acc[8][4] = {};
    for (int khf = 0; khf < 2; khf++) {
        __syncthreads();
        {
            int nn = (t & 31) * 4;
            int kk = t >> 5;
#pragma unroll
            for (int q = 0; q < 4; q++) {
                int row = kk + q * 8;
                *(float4*)&Bs[row][nn] =
                    *(const float4*)&dw[(khf * 32 + row) * 12544 + n0 + nn];
            }
        }
        __syncthreads();
#pragma unroll
        for (int kk = 0; kk < 32; kk++) {
            int kg = khf * 32 + kk;
            float a[8];
#pragma unroll
            for (int i = 0; i < 8; i++) a[i] = Zs[kg][tr * 8 + i];
            float4 b4 = *(const float4*)&Bs[kk][tc * 4];
            float bb[4] = {b4.x, b4.y, b4.z, b4.w};
#pragma unroll
            for (int i = 0; i < 8; i++)
#pragma unroll
                for (int j = 0; j < 4; j++) acc[i][j] += a[i] * bb[j];
        }
    }
#pragma unroll
    for (int i = 0; i < 8; i++) {
        int m = m0 + tr * 8 + i;
#pragma unroll
        for (int j = 0; j < 4; j++) {
            int f = n0 + tc * 4 + j;
            float v = acc[i][j] + db[f];
            g_dh[(size_t)m * 12544 + f] = __float2half(v);
        }
    }
}

// ---------------- K8: deconv2 single-pass (fp16 image, full-channel lanes) --------
__global__ __launch_bounds__(256) void k_deconv2p(const float* __restrict__ b2,
                                                  float* __restrict__ out) {
    extern __shared__ __align__(16) char dsm[];
    __half* gsm = (__half*)dsm;
    float* wsm = (float*)(dsm + 57344);
    int img = blockIdx.x;
    int half = blockIdx.y;
    int y0 = half * 14;
    int gbase = half * 6;
    int t = threadIdx.x;
    int wrp = t >> 5, lane = t & 31;
    float bias = b2[0];

    {
        const uint4* src =
            (const uint4*)(g_g1h + (size_t)(img * 196 + gbase * 14) * 256);
        uint4* dst = (uint4*)gsm;
        for (int e = t; e < 3584; e += 256) dst[e] = src[e];
    }
    {
        const float4* src = (const float4*)g_w2c;
        float4* dst = (float4*)wsm;
        for (int e = t; e < 2304; e += 256) dst[e] = src[e];
    }
    __syncthreads();

    for (int p = wrp; p < 392; p += 8) {
        int yy = p / 28, x = p % 28;
        int y = y0 + yy;
        int py = y & 1, px = x & 1;
        int cls = py * 2 + px;
        int sy = y >> 1, sx = x >> 1;
        int TY = 3 - py, TX = 3 - px;
        float r = 0.f;
        for (int ty = 0; ty < TY; ty++) {
            int iy = sy + ty + py - 1;
            if ((unsigned)iy >= 14u) continue;
            int gy = iy - gbase;
            for (int tx = 0; tx < TX; tx++) {
                int ix = sx + tx + px - 1;
                if ((unsigned)ix >= 14u) continue;
                const __half2* gp =
                    (const __half2*)(gsm + (gy * 14 + ix) * 256 + lane * 8);
                const float* wp = wsm + (cls * 9 + ty * TX + tx) * 256 + lane * 8;
#pragma unroll
                for (int q = 0; q < 4; q++) {
                    float2 g2 = __half22float2(gp[q]);
                    r += g2.x * wp[2 * q] + g2.y * wp[2 * q + 1];
                }
            }
        }
#pragma unroll
        for (int s = 16; s > 0; s >>= 1) r += __shfl_xor_sync(0xffffffffu, r, s);
        if (lane == 0) {
            float v = r + bias;
            out[img * 784 + y * 28 + x] = 1.f / (1.f + expf(-v));
        }
    }
}

// ---------------- launch ----------------
static constexpr int SMEM_ENC = 3 * 65536;
static constexpr int SMEM_DEC = 3 * 32768;
static constexpr int SMEM_D2 = 57344 + 36864;

extern "C" void kernel_launch(void* const* d_in, const int* in_sizes, int n_in,
                              void* d_out, int out_size) {
    const float* x   = (const float*)d_in[0];
    const float* c1w = (const float*)d_in[1];
    const float* c1b = (const float*)d_in[2];
    const float* c2w = (const float*)d_in[3];
    const float* c2b = (const float*)d_in[4];
    const float* ew  = (const float*)d_in[5];
    const float* eb  = (const float*)d_in[6];
    const float* emb = (const float*)d_in[7];
    const float* dw  = (const float*)d_in[8];
    const float* db  = (const float*)d_in[9];
    const float* d1w = (const float*)d_in[10];
    const float* d1b = (const float*)d_in[11];
    const float* d2w = (const float*)d_in[12];
    const float* d2b = (const float*)d_in[13];
    float* out = (float*)d_out;

    void *pa1h, *pa1l, *pw2h, *pw2l, *pdh, *pw1h, *ph2, *pg1;
    cudaGetSymbolAddress(&pa1h, g_a1h);
    cudaGetSymbolAddress(&pa1l, g_a1l);
    cudaGetSymbolAddress(&pw2h, g_w2h);
    cudaGetSymbolAddress(&pw2l, g_w2l);
    cudaGetSymbolAddress(&pdh, g_dh);
    cudaGetSymbolAddress(&pw1h, g_w1h);
    cudaGetSymbolAddress(&ph2, g_h2);
    cudaGetSymbolAddress(&pg1, g_g1h);

    cudaFuncSetAttribute((const void*)k_hmma_enc,
                         cudaFuncAttributeMaxDynamicSharedMemorySize, SMEM_ENC);
    cudaFuncSetAttribute((const void*)k_hmma_dec,
                         cudaFuncAttributeMaxDynamicSharedMemorySize, SMEM_DEC);
    cudaFuncSetAttribute((const void*)k_deconv2p,
                         cudaFuncAttributeMaxDynamicSharedMemorySize, SMEM_D2);

    k_prep<<<14180, 256>>>(x, c1w, c1b, c2w, d1w, d2w);
    k_hmma_enc<<<dim3(392, 2), 512, SMEM_ENC>>>(
        (const __half*)pa1h, (const __half*)pa1l, (const __half*)pw2h,
        (const __half*)pw2l, c2b, (float*)ph2);
    k_enc_part<<<dim3(49, 4), 256>>>((const float*)ph2, ew);
    k_redargmin<<<256, 256>>>(emb, eb);
    k_decfc<<<dim3(98, 8), 256>>>(dw, db);
    k_hmma_dec<<<dim3(196, 2, 4), 512, SMEM_DEC>>>(
        (const __half*)pdh, (const __half*)pw1h, d1b, (__half*)pg1);
    k_deconv2p<<<dim3(512, 2), 256, SMEM_D2>>>(d2b, out);
}

// round 14
// speedup vs baseline: 1.0666x; 1.0666x over previous
#include <cuda_runtime.h>
#include <cuda_fp16.h>
#include <math.h>
#include <stdint.h>

// ============================ helpers ============================
__device__ __forceinline__ uint32_t smem_to_u32(const void* p) {
    uint32_t a;
    asm("{ .reg .u64 t; cvta.to.shared.u64 t, %1; cvt.u32.u64 %0, t; }"
        : "=r"(a) : "l"(p));
    return a;
}
__device__ __forceinline__ void cp_async16(uint32_t smem, const void* g, uint32_t sz) {
    asm volatile("cp.async.cg.shared.global [%0], [%1], 16, %2;"
                 :: "r"(smem), "l"(g), "r"(sz) : "memory");
}
#define CP_COMMIT() asm volatile("cp.async.commit_group;" ::: "memory")
#define CP_WAIT1() asm volatile("cp.async.wait_group 1;" ::: "memory")
#define CP_WAIT0() asm volatile("cp.async.wait_group 0;" ::: "memory")
#define LDSM4(r0, r1, r2, r3, addr) \
    asm volatile("ldmatrix.sync.aligned.m8n8.x4.shared.b16 {%0,%1,%2,%3}, [%4];" \
                 : "=r"(r0), "=r"(r1), "=r"(r2), "=r"(r3) : "r"(addr))
__device__ __forceinline__ void mma16816(float* c, const uint32_t* a, uint32_t b0,
                                         uint32_t b1) {
    asm volatile(
        "mma.sync.aligned.m16n8k16.row.col.f32.f16.f16.f32 "
        "{%0,%1,%2,%3}, {%4,%5,%6,%7}, {%8,%9}, {%0,%1,%2,%3};"
        : "+f"(c[0]), "+f"(c[1]), "+f"(c[2]), "+f"(c[3])
        : "r"(a[0]), "r"(a[1]), "r"(a[2]), "r"(a[3]), "r"(b0), "r"(b1));
}
#define SWZ(x) ((x) ^ (((x) >> 3) & 0x70))

// ============================ scratch (device globals) ============================
__device__ __align__(16) __half g_a1h[12845056];   // conv2 A limbs [pos][ch]
__device__ __align__(16) __half g_a1l[12845056];
__device__ __align__(16) __half g_w2h[1048576];    // conv2 B limbs [n][4096]
__device__ __align__(16) __half g_w2l[1048576];
__device__ __align__(16) __half g_dh[6422528];     // deconv1 A (hi only) [pos][ch]
__device__ __align__(16) __half g_w1h[1638400];    // deconv1 parity weights (hi only)
__device__ float g_w2c[9216];        // deconv2 parity-combined weights [4][9][256]
__device__ float g_h2[3211264];      // pooled conv2 out (atomicMax target)
__device__ float g_encp[1605632];    // encoder split-K partials (98 chunks)
__device__ float g_z[32768];         // rows 0..255 z_e, 256..511 z_q
__device__ __align__(16) __half g_g1h[25690112];   // deconv1 out (fp16)

// ============== fused prep: zero | conv1pool | wsplit2 | wcomb | wcomb2 ===========
// block ranges: [0,3136) zero, [3136,6720) conv1pool, [6720,7744) wsplit2,
//               [7744,14144) wcomb, [14144,14180) wcomb2
__global__ __launch_bounds__(256) void k_prep(const float* __restrict__ x,
                                              const float* __restrict__ w1,
                                              const float* __restrict__ b1,
                                              const float* __restrict__ w2,
                                              const float* __restrict__ d1w,
                                              const float* __restrict__ d2w) {
    __shared__ __align__(16) char sm[4352];
    const int b = blockIdx.x;
    const int t = threadIdx.x;
    if (b < 3136) {
        int i = b * 256 + t;
        if (i < 802816) *(((uint4*)g_h2) + i) = make_uint4(0u, 0u, 0u, 0u);
    } else if (b < 6720) {
        int bb = b - 3136;
        int py = bb % 14;
        int img = bb / 14;
        int c = t;
        float(*xs)[32] = (float(*)[32])sm;
        for (int e = t; e < 5 * 32; e += 256) {
            int r = e / 32, cc = e % 32;
            int iy = 2 * py - 1 + r;
            int ix = cc - 1;
            float v = 0.f;
            if (iy >= 0 && iy < 28 && ix >= 0 && ix < 28)
                v = x[(img * 28 + iy) * 28 + ix];
            xs[r][cc] = v;
        }
        float w[16];
#pragma unroll
        for (int i = 0; i < 16; i++) w[i] = w1[i * 256 + c];
        float bias = b1[c];
        __syncthreads();
        for (int px = 0; px < 14; px++) {
            float mv = -1e30f;
#pragma unroll
            for (int dy = 0; dy < 2; dy++)
#pragma unroll
                for (int dx = 0; dx < 2; dx++) {
                    float v = bias;
#pragma unroll
                    for (int ky = 0; ky < 4; ky++)
#pragma unroll
                        for (int kx = 0; kx < 4; kx++)
                            v += xs[dy + ky][2 * px + dx + kx] * w[ky * 4 + kx];
                    mv = fmaxf(mv, v);
                }
            float val = fmaxf(mv, 0.f);
            int idx = ((img * 14 + py) * 14 + px) * 256 + c;
            __half h = __float2half(val);
            g_a1h[idx] = h;
            g_a1l[idx] = __float2half(val - __half2float(h));
        }
    } else if (b < 7744) {
        int i = b - 6720;
        int k0 = (i & 127) * 32, n0 = (i >> 7) * 32;
        float(*tile)[33] = (float(*)[33])sm;
        int tx = t & 31, ty = t >> 5;
#pragma unroll
        for (int r = 0; r < 32; r += 8)
            tile[ty + r][tx] = w2[(k0 + ty + r) * 256 + n0 + tx];
        __syncthreads();
#pragma unroll
        for (int r = 0; r < 32; r += 8) {
            float v = tile[tx][ty + r];
            int n = n0 + ty + r;
            int idx = n * 4096 + k0 + tx;
            __half h = __float2half(v);
            g_w2h[idx] = h;
            g_w2l[idx] = __float2half(v - __half2float(h));
        }
    } else if (b < 14144) {
        int idx = (b - 7744) * 256 + t;
        int c, base;
        if (idx < 589824) { c = 0; base = 0; }
        else if (idx < 983040) { c = 1; base = 589824; }
        else if (idx < 1376256) { c = 2; base = 983040; }
        else { c = 3; base = 1376256; }
        int py = c >> 1, px = c & 1;
        int TX = 3 - px;
        int Kc = (3 - py) * TX * 256;
        int rem = idx - base;
        int n = rem / Kc;
        int k = rem % Kc;
        int tap = k >> 8, cin = k & 255;
        int ty = tap / TX, tx = tap % TX;
        int kys, kyn, kxs, kxn;
        if (py == 0) { kys = (ty == 0) ? 0 : (ty == 1) ? 1 : 3; kyn = (ty == 1) ? 2 : 1; }
        else { kys = ty * 2; kyn = 2; }
        if (px == 0) { kxs = (tx == 0) ? 0 : (tx == 1) ? 1 : 3; kxn = (tx == 1) ? 2 : 1; }
        else { kxs = tx * 2; kxn = 2; }
        float s = 0.f;
        for (int a = 0; a < kyn; a++)
            for (int bb = 0; bb < kxn; bb++)
                s += d1w[(((kys + a) * 4 + kxs + bb) * 256 + cin) * 256 + n];
        g_w1h[idx] = __float2half(s);
    } else {
        int i = (b - 14144) * 256 + t;
        if (i >= 9216) return;
        int cls = i / 2304;
        int rem = i % 2304;
        int tap = rem >> 8;
        int cin = rem & 255;
        int py = cls >> 1, px = cls & 1;
        int TX = 3 - px, TY = 3 - py;
        if (tap >= TY * TX) { g_w2c[i] = 0.f; return; }
        int ty = tap / TX, tx = tap % TX;
        int kys, kyn, kxs, kxn;
        if (py == 0) { kys = (ty == 0) ? 0 : (ty == 1) ? 1 : 3; kyn = (ty == 1) ? 2 : 1; }
        else { kys = ty * 2; kyn = 2; }
        if (px == 0) { kxs = (tx == 0) ? 0 : (tx == 1) ? 1 : 3; kxn = (tx == 1) ? 2 : 1; }
        else { kxs = tx * 2; kxn = 2; }
        float s = 0.f;
        for (int a = 0; a < kyn; a++)
            for (int bb = 0; bb < kxn; bb++)
                s += d2w[((kys + a) * 4 + kxs + bb) * 256 + cin];
        g_w2c[i] = s;
    }
}

// ============== encoder HMMA implicit-GEMM conv2 (R11 config, 256 threads) ========
__global__ __launch_bounds__(256, 1) void k_hmma_enc(
    const __half* __restrict__ a0p, const __half* __restrict__ a1p,
    const __half* __restrict__ b0p, const __half* __restrict__ b1p,
    const float* __restrict__ bias, float* __restrict__ outpool) {
    constexpr int STAGE = 65536;
    extern __shared__ __align__(1024) char smem[];
    const uint32_t sb = smem_to_u32(smem);
    const int t = threadIdx.x;
    const int wid = t >> 5;
    const int lane = t & 31;
    const int wr = wid & 1;
    const int wc = wid >> 1;
    const int m0 = blockIdx.x * 128;
    const int n0 = blockIdx.y * 128;

    const int rr = t >> 3;
    const int seg = t & 7;
    int imgA[4], oyA[4], oxA[4];
    uint32_t stsO[4];
#pragma unroll
    for (int j = 0; j < 4; j++) {
        int m = m0 + rr + 32 * j;
        imgA[j] = m / 196;
        int p = m % 196;
        oyA[j] = p / 14;
        oxA[j] = p % 14;
        stsO[j] = SWZ((uint32_t)((rr + 32 * j) * 128 + seg * 16));
    }

    float acc[4][4][4];
#pragma unroll
    for (int i = 0; i < 4; i++)
#pragma unroll
        for (int j = 0; j < 4; j++)
#pragma unroll
            for (int q = 0; q < 4; q++) acc[i][j][q] = 0.f;

    const int arow = wr * 64 + (lane & 15);
    const uint32_t acolbase = (uint32_t)((lane >> 4) * 16);
    const int brow = wc * 32 + (lane & 7) + (lane >> 4) * 8;
    const uint32_t bcolbase = (uint32_t)(((lane >> 3) & 1) * 16);

    auto issue = [&](int s, int buf) {
        const int tap = s >> 2;
        const int ky = tap >> 2, kx = tap & 3;
        const int ch0 = (s & 3) * 64;
        const uint32_t sbuf = sb + (uint32_t)buf * STAGE;
#pragma unroll
        for (int j = 0; j < 4; j++) {
            int iy = oyA[j] - 1 + ky;
            int ix = oxA[j] - 1 + kx;
            bool v = ((unsigned)iy < 14u) && ((unsigned)ix < 14u);
            int pos = imgA[j] * 196 + iy * 14 + ix;
            int aoff = v ? (pos * 256 + ch0 + seg * 8) : 0;
            uint32_t sz = v ? 16u : 0u;
            cp_async16(sbuf + stsO[j], a0p + aoff, sz);
            cp_async16(sbuf + 16384 + stsO[j], a1p + aoff, sz);
            size_t boff = (size_t)(n0 + rr + 32 * j) * 4096 + s * 64 + seg * 8;
            cp_async16(sbuf + 32768 + stsO[j], b0p + boff, 16u);
            cp_async16(sbuf + 49152 + stsO[j], b1p + boff, 16u);
        }
    };

    uint32_t af[2][2][4][4];
    uint32_t bf[2][2][2][4];
    auto ldfrag = [&](uint32_t abase, uint32_t bbase, int slot, int kk) {
        const uint32_t acol = acolbase + kk * 32;
#pragma unroll
        for (int la = 0; la < 2; la++)
#pragma unroll
            for (int mt = 0; mt < 4; mt++) {
                int row = arow + mt * 16;
                LDSM4(af[slot][la][mt][0], af[slot][la][mt][1], af[slot][la][mt][2],
                      af[slot][la][mt][3],
                      abase + la * 16384 + row * 128 + (acol ^ ((row & 7) * 16)));
            }
        const uint32_t bcol = bcolbase + kk * 32;
#pragma unroll
        for (int lb = 0; lb < 2; lb++)
#pragma unroll
            for (int nt2 = 0; nt2 < 2; nt2++) {
                int row = brow + nt2 * 16;
                LDSM4(bf[slot][lb][nt2][0], bf[slot][lb][nt2][1], bf[slot][lb][nt2][2],
                      bf[slot][lb][nt2][3],
                      bbase + lb * 16384 + row * 128 + (bcol ^ ((row & 7) * 16)));
            }
    };

    issue(0, 0);
    CP_COMMIT();
    issue(1, 1);
    CP_COMMIT();

    int buf = 0;
    for (int s = 0; s < 64; s++) {
        if (s + 1 < 64) CP_WAIT1(); else CP_WAIT0();
        __syncthreads();
        if (s + 2 < 64) {
            int nb = buf + 2;
            if (nb >= 3) nb -= 3;
            issue(s + 2, nb);
            CP_COMMIT();
        }
        const uint32_t abase = sb + (uint32_t)buf * STAGE;
        const uint32_t bbase = abase + 32768;
        ldfrag(abase, bbase, 0, 0);
#pragma unroll
        for (int kk = 0; kk < 4; kk++) {
            const int cur = kk & 1;
            if (kk < 3) ldfrag(abase, bbase, cur ^ 1, kk + 1);
#pragma unroll
            for (int p = 0; p < 3; p++) {
                const int la = (p == 2) ? 1 : 0;
                const int lb = (p == 1) ? 1 : 0;
#pragma unroll
                for (int mt = 0; mt < 4; mt++)
#pragma unroll
                    for (int nt = 0; nt < 4; nt++)
                        mma16816(acc[mt][nt], af[cur][la][mt],
                                 bf[cur][lb][nt >> 1][(nt & 1) * 2],
                                 bf[cur][lb][nt >> 1][(nt & 1) * 2 + 1]);
            }
        }
        if (++buf == 3) buf = 0;
    }

    unsigned* outp = (unsigned*)outpool;
#pragma unroll
    for (int mt = 0; mt < 4; mt++) {
#pragma unroll
        for (int nt = 0; nt < 4; nt++) {
            int col = n0 + wc * 32 + nt * 8 + (lane & 3) * 2;
            float b0v = bias[col], b1v = bias[col + 1];
#pragma unroll
            for (int h8 = 0; h8 < 2; h8++) {
                int m = m0 + wr * 64 + mt * 16 + (lane >> 2) + h8 * 8;
                int img = m / 196;
                int p = m % 196;
                int py = (p / 14) >> 1;
                int px = (p % 14) >> 1;
                size_t base = (size_t)((img * 7 + py) * 7 + px) * 256 + col;
                float v0 = fmaxf(acc[mt][nt][h8 * 2] + b0v, 0.f);
                float v1 = fmaxf(acc[mt][nt][h8 * 2 + 1] + b1v, 0.f);
                atomicMax(outp + base, __float_as_uint(v0));
                atomicMax(outp + base + 1, __float_as_uint(v1));
            }
        }
    }
}

// ============== decoder HMMA (R11 config): parity, single-limb, fp16 out ==========
__global__ __launch_bounds__(256, 1) void k_hmma_dec(
    const __half* __restrict__ a0p, const __half* __restrict__ b0p,
    const float* __restrict__ bias, __half* __restrict__ out) {
    constexpr int STAGE = 32768;
    extern __shared__ __align__(1024) char smem[];
    const uint32_t sb = smem_to_u32(smem);
    const int t = threadIdx.x;
    const int wid = t >> 5;
    const int lane = t & 31;
    const int wr = wid & 1;
    const int wc = wid >> 1;
    const int m0 = blockIdx.x * 128;
    const int n0 = blockIdx.y * 128;
    const int cls = blockIdx.z;
    const int py = cls >> 1, px = cls & 1;
    const int TX = 3 - px;
    const int TY = 3 - py;
    const int nst = TY * TX * 4;
    const int Kc = TY * TX * 256;
    const int woff = (cls == 0) ? 0 : (cls == 1) ? 589824 : (cls == 2) ? 983040
                                                                       : 1376256;

    const int rr = t >> 3;
    const int seg = t & 7;
    int imgA[4], syA[4], sxA[4];
    uint32_t stsO[4];
#pragma unroll
    for (int j = 0; j < 4; j++) {
        int m = m0 + rr + 32 * j;
        imgA[j] = m / 49;
        int p = m % 49;
        syA[j] = p / 7;
        sxA[j] = p % 7;
        stsO[j] = SWZ((uint32_t)((rr + 32 * j) * 128 + seg * 16));
    }

    float acc[4][4][4];
#pragma unroll
    for (int i = 0; i < 4; i++)
#pragma unroll
        for (int j = 0; j < 4; j++)
#pragma unroll
            for (int q = 0; q < 4; q++) acc[i][j][q] = 0.f;

    const int arow = wr * 64 + (lane & 15);
    const uint32_t acolbase = (uint32_t)((lane >> 4) * 16);
    const int brow = wc * 32 + (lane & 7) + (lane >> 4) * 8;
    const uint32_t bcolbase = (uint32_t)(((lane >> 3) & 1) * 16);

    auto issue = [&](int s, int buf) {
        const int tap = s >> 2;
        const int ch0 = (s & 3) * 64;
        const int ty = tap / TX, tx = tap % TX;
        const uint32_t sbuf = sb + (uint32_t)buf * STAGE;
#pragma unroll
        for (int j = 0; j < 4; j++) {
            int iy = syA[j] + ty + (py - 1);
            int ix = sxA[j] + tx + (px - 1);
            bool v = ((unsigned)iy < 7u) && ((unsigned)ix < 7u);
            int pos = imgA[j] * 49 + iy * 7 + ix;
            int aoff = v ? (pos * 256 + ch0 + seg * 8) : 0;
            uint32_t sz = v ? 16u : 0u;
            cp_async16(sbuf + stsO[j], a0p + aoff, sz);
            size_t boff = (size_t)woff + (size_t)(n0 + rr + 32 * j) * Kc + s * 64 +
                          seg * 8;
            cp_async16(sbuf + 16384 + stsO[j], b0p + boff, 16u);
        }
    };

    uint32_t af[2][4][4];
    uint32_t bf[2][2][4];
    auto ldfrag = [&](uint32_t abase, uint32_t bbase, int slot, int kk) {
        const uint32_t acol = acolbase + kk * 32;
#pragma unroll
        for (int mt = 0; mt < 4; mt++) {
            int row = arow + mt * 16;
            LDSM4(af[slot][mt][0], af[slot][mt][1], af[slot][mt][2], af[slot][mt][3],
                  abase + row * 128 + (acol ^ ((row & 7) * 16)));
        }
        const uint32_t bcol = bcolbase + kk * 32;
#pragma unroll
        for (int nt2 = 0; nt2 < 2; nt2++) {
            int row = brow + nt2 * 16;
            LDSM4(bf[slot][nt2][0], bf[slot][nt2][1], bf[slot][nt2][2],
                  bf[slot][nt2][3],
                  bbase + row * 128 + (bcol ^ ((row & 7) * 16)));
        }
    };

    issue(0, 0);
    CP_COMMIT();
    issue(1, 1);
    CP_COMMIT();

    int buf = 0;
    for (int s = 0; s < nst; s++) {
        if (s + 1 < nst) CP_WAIT1(); else CP_WAIT0();
        __syncthreads();
        if (s + 2 < nst) {
            int nb = buf + 2;
            if (nb >= 3) nb -= 3;
            issue(s + 2, nb);
            CP_COMMIT();
        }
        const uint32_t abase = sb + (uint32_t)buf * STAGE;
        const uint32_t bbase = abase + 16384;
        ldfrag(abase, bbase, 0, 0);
#pragma unroll
        for (int kk = 0; kk < 4; kk++) {
            const int cur = kk & 1;
            if (kk < 3) ldfrag(abase, bbase, cur ^ 1, kk + 1);
#pragma unroll
            for (int mt = 0; mt < 4; mt++)
#pragma unroll
                for (int nt = 0; nt < 4; nt++)
                    mma16816(acc[mt][nt], af[cur][mt],
                             bf[cur][nt >> 1][(nt & 1) * 2],
                             bf[cur][nt >> 1][(nt & 1) * 2 + 1]);
        }
        if (++buf == 3) buf = 0;
    }

#pragma unroll
    for (int mt = 0; mt < 4; mt++) {
#pragma unroll
        for (int nt = 0; nt < 4; nt++) {
            int col = n0 + wc * 32 + nt * 8 + (lane & 3) * 2;
            float b0v = bias[col], b1v = bias[col + 1];
#pragma unroll
            for (int half8 = 0; half8 < 2; half8++) {
                int m = m0 + wr * 64 + mt * 16 + (lane >> 2) + half8 * 8;
                int img = m / 49;
                int p = m % 49;
                int oy = 2 * (p / 7) + py;
                int ox = 2 * (p % 7) + px;
                float v0 = fmaxf(acc[mt][nt][half8 * 2] + b0v, 0.f);
                float v1 = fmaxf(acc[mt][nt][half8 * 2 + 1] + b1v, 0.f);
                __half2 hv = __floats2half2_rn(v0, v1);
                *(__half2*)(out + (size_t)((img * 14 + oy) * 14 + ox) * 256 + col) = hv;
            }
        }
    }
}

// ---------------- K4: encoder FC split-K (98 chunks of K=128) ----------------
__global__ __launch_bounds__(256) void k_enc_part(const float* __restrict__ h2,
                                                  const float* __restrict__ ew) {
    int kc = blockIdx.x;
    int b0 = blockIdx.y * 64;
    __shared__ float As[8][64];
    __shared__ float Bs[8][64];
    int t = threadIdx.x;
    int abb = t >> 2, akk = (t & 3) * 2;
    int bkk = t >> 5, bll = (t & 31) * 2;
    int tr = t >> 4, tc = t & 15;
    float acc[4][4] = {};
    int kbase = kc * 128;
    for (int ks = 0; ks < 128; ks += 8) {
        int k0 = kbase + ks;
        float2 av = *(const float2*)&h2[(b0 + abb) * 12544 + k0 + akk];
        float2 bv = *(const float2*)&ew[(k0 + bkk) * 64 + bll];
        __syncthreads();
        As[akk][abb] = av.x;
        As[akk + 1][abb] = av.y;
        *(float2*)&Bs[bkk][bll] = bv;
        __syncthreads();
#pragma unroll
        for (int kk = 0; kk < 8; kk++) {
            float a[4], b[4];
#pragma unroll
            for (int i = 0; i < 4; i++) a[i] = As[kk][tr * 4 + i];
#pragma unroll
            for (int j = 0; j < 4; j++) b[j] = Bs[kk][tc * 4 + j];
#pragma unroll
            for (int i = 0; i < 4; i++)
#pragma unroll
                for (int j = 0; j < 4; j++) acc[i][j] += a[i] * b[j];
        }
    }
#pragma unroll
    for (int i = 0; i < 4; i++)
#pragma unroll
        for (int j = 0; j < 4; j++)
            g_encp[(kc * 256 + b0 + tr * 4 + i) * 64 + tc * 4 + j] = acc[i][j];
}

// ---- K5: fused parallel reduce (4 groups over 98 partials) + argmin + gather ----
__global__ __launch_bounds__(256) void k_redargmin(const float* __restrict__ emb,
                                                   const float* __restrict__ eb) {
    int b = blockIdx.x;
    __shared__ float ps[4][64];
    __shared__ float zb[64];
    __shared__ float ds[256];
    __shared__ int ki[256];
    int t = threadIdx.x;
    {
        int lat = t & 63;
        int g = t >> 6;
        float s = 0.f;
        for (int kc = g; kc < 98; kc += 4) s += g_encp[kc * 16384 + b * 64 + lat];
        ps[g][lat] = s;
    }
    __syncthreads();
    if (t < 64) {
        float z = eb[t] + ((ps[0][t] + ps[1][t]) + (ps[2][t] + ps[3][t]));
        zb[t] = z;
        g_z[b * 64 + t] = z;
    }
    __syncthreads();
    float d = 0.f;
    const float* e = emb + t * 64;
#pragma unroll 8
    for (int j = 0; j < 64; j++) {
        float df = zb[j] - e[j];
        d += df * df;
    }
    ds[t] = d;
    ki[t] = t;
    __syncthreads();
    for (int s = 128; s > 0; s >>= 1) {
        if (t < s) {
            float d2 = ds[t + s];
            int k2 = ki[t + s];
            if (d2 < ds[t] || (d2 == ds[t] && k2 < ki[t])) { ds[t] = d2; ki[t] = k2; }
        }
        __syncthreads();
    }
    int kb = ki[0];
    if (t < 64) g_z[(256 + b) * 64 + t] = emb[kb * 64 + t];
}

// ---------------- K6: decoder FC -> fp16 hi plane only ----------------
__global__ __launch_bounds__(256) void k_decfc(const float* __restrict__ dw,
                                               const float* __restrict__ db) {
    int n0 = blockIdx.x * 128;
    int m0 = blockIdx.y * 64;
    __shared__ float Zs[64][64];
    __shared__ float Bs[32][128];
    int t = threadIdx.x;
    {
        int rr = t >> 2, kk0 = (t & 3) * 16;
        const float* zp = &g_z[(m0 + rr) * 64 + kk0];
#pragma unroll
        for (int q = 0; q < 4; q++) {
            float4 v = *(const float4*)(zp + q * 4);
            Zs[kk0 + q * 4 + 0][rr] = v.x; Zs[kk0 + q * 4 + 1][rr] = v.y;
            Zs[kk0 + q * 4 + 2][rr] = v.z; Zs[kk0 + q * 4 + 3][rr] = v.w;
        }
    }
    int tr = t >> 5;
    int tc = t & 31;
    float acc[8][4] = {};
    for (int khf = 0; khf < 2; khf++) {
        __syncthreads();
        {
            int nn = (t & 31) * 4;
            int kk = t >> 5;
#pragma unroll
            for (int q = 0; q < 4; q++) {
                int row = kk + q * 8;
                *(float4*)&Bs[row][nn] =
                    *(const float4*)&dw[(khf * 32 + row) * 12544 + n0 + nn];
            }
        }
        __syncthreads();
#pragma unroll
        for (int kk = 0; kk < 32; kk++) {
            int kg = khf * 32 + kk;
            float a[8];
#pragma unroll
            for (int i = 0; i < 8; i++) a[i] = Zs[kg][tr * 8 + i];
            float4 b4 = *(const float4*)&Bs[kk][tc * 4];
            float bb[4] = {b4.x, b4.y, b4.z, b4.w};
#pragma unroll
            for (int i = 0; i < 8; i++)
#pragma unroll
                for (int j = 0; j < 4; j++) acc[i][j] += a[i] * bb[j];
        }
    }
#pragma unroll
    for (int i = 0; i < 8; i++) {
        int m = m0 + tr * 8 + i;
#pragma unroll
        for (int j = 0; j < 4; j++) {
            int f = n0 + tc * 4 + j;
            float v = acc[i][j] + db[f];
            g_dh[(size_t)m * 12544 + f] = __float2half(v);
        }
    }
}

// ---------------- K8: deconv2 single-pass (fp16 image, full-channel lanes) --------
__global__ __launch_bounds__(256) void k_deconv2p(const float* __restrict__ b2,
                                                  float* __restrict__ out) {
    extern __shared__ __align__(16) char dsm[];
    __half* gsm = (__half*)dsm;
    float* wsm = (float*)(dsm + 57344);
    int img = blockIdx.x;
    int half = blockIdx.y;
    int y0 = half * 14;
    int gbase = half * 6;
    int t = threadIdx.x;
    int wrp = t >> 5, lane = t & 31;
    float bias = b2[0];

    {
        const uint4* src =
            (const uint4*)(g_g1h + (size_t)(img * 196 + gbase * 14) * 256);
        uint4* dst = (uint4*)gsm;
        for (int e = t; e < 3584; e += 256) dst[e] = src[e];
    }
    {
        const float4* src = (const float4*)g_w2c;
        float4* dst = (float4*)wsm;
        for (int e = t; e < 2304; e += 256) dst[e] = src[e];
    }
    __syncthreads();

    for (int p = wrp; p < 392; p += 8) {
        int yy = p / 28, x = p % 28;
        int y = y0 + yy;
        int py = y & 1, px = x & 1;
        int cls = py * 2 + px;
        int sy = y >> 1, sx = x >> 1;
        int TY = 3 - py, TX = 3 - px;
        float r = 0.f;
        for (int ty = 0; ty < TY; ty++) {
            int iy = sy + ty + py - 1;
            if ((unsigned)iy >= 14u) continue;
            int gy = iy - gbase;
            for (int tx = 0; tx < TX; tx++) {
                int ix = sx + tx + px - 1;
                if ((unsigned)ix >= 14u) continue;
                const __half2* gp =
                    (const __half2*)(gsm + (gy * 14 + ix) * 256 + lane * 8);
                const float* wp = wsm + (cls * 9 + ty * TX + tx) * 256 + lane * 8;
#pragma unroll
                for (int q = 0; q < 4; q++) {
                    float2 g2 = __half22float2(gp[q]);
                    r += g2.x * wp[2 * q] + g2.y * wp[2 * q + 1];
                }
            }
        }
#pragma unroll
        for (int s = 16; s > 0; s >>= 1) r += __shfl_xor_sync(0xffffffffu, r, s);
        if (lane == 0) {
            float v = r + bias;
            out[img * 784 + y * 28 + x] = 1.f / (1.f + expf(-v));
        }
    }
}

// ---------------- launch ----------------
static constexpr int SMEM_ENC = 3 * 65536;
static constexpr int SMEM_DEC = 3 * 32768;
static constexpr int SMEM_D2 = 57344 + 36864;

extern "C" void kernel_launch(void* const* d_in, const int* in_sizes, int n_in,
                              void* d_out, int out_size) {
    const float* x   = (const float*)d_in[0];
    const float* c1w = (const float*)d_in[1];
    const float* c1b = (const float*)d_in[2];
    const float* c2w = (const float*)d_in[3];
    const float* c2b = (const float*)d_in[4];
    const float* ew  = (const float*)d_in[5];
    const float* eb  = (const float*)d_in[6];
    const float* emb = (const float*)d_in[7];
    const float* dw  = (const float*)d_in[8];
    const float* db  = (const float*)d_in[9];
    const float* d1w = (const float*)d_in[10];
    const float* d1b = (const float*)d_in[11];
    const float* d2w = (const float*)d_in[12];
    const float* d2b = (const float*)d_in[13];
    float* out = (float*)d_out;

    void *pa1h, *pa1l, *pw2h, *pw2l, *pdh, *pw1h, *ph2, *pg1;
    cudaGetSymbolAddress(&pa1h, g_a1h);
    cudaGetSymbolAddress(&pa1l, g_a1l);
    cudaGetSymbolAddress(&pw2h, g_w2h);
    cudaGetSymbolAddress(&pw2l, g_w2l);
    cudaGetSymbolAddress(&pdh, g_dh);
    cudaGetSymbolAddress(&pw1h, g_w1h);
    cudaGetSymbolAddress(&ph2, g_h2);
    cudaGetSymbolAddress(&pg1, g_g1h);

    cudaFuncSetAttribute((const void*)k_hmma_enc,
                         cudaFuncAttributeMaxDynamicSharedMemorySize, SMEM_ENC);
    cudaFuncSetAttribute((const void*)k_hmma_dec,
                         cudaFuncAttributeMaxDynamicSharedMemorySize, SMEM_DEC);
    cudaFuncSetAttribute((const void*)k_deconv2p,
                         cudaFuncAttributeMaxDynamicSharedMemorySize, SMEM_D2);

    k_prep<<<14180, 256>>>(x, c1w, c1b, c2w, d1w, d2w);
    k_hmma_enc<<<dim3(392, 2), 256, SMEM_ENC>>>(
        (const __half*)pa1h, (const __half*)pa1l, (const __half*)pw2h,
        (const __half*)pw2l, c2b, (float*)ph2);
    k_enc_part<<<dim3(98, 4), 256>>>((const float*)ph2, ew);
    k_redargmin<<<256, 256>>>(emb, eb);
    k_decfc<<<dim3(98, 8), 256>>>(dw, db);
    k_hmma_dec<<<dim3(196, 2, 4), 256, SMEM_DEC>>>(
        (const __half*)pdh, (const __half*)pw1h, d1b, (__half*)pg1);
    k_deconv2p<<<dim3(512, 2), 256, SMEM_D2>>>(d2b, out);
}

// round 15
// speedup vs baseline: 1.0763x; 1.0091x over previous
#include <cuda_runtime.h>
#include <cuda_fp16.h>
#include <math.h>
#include <stdint.h>

// ============================ helpers ============================
__device__ __forceinline__ uint32_t smem_to_u32(const void* p) {
    uint32_t a;
    asm("{ .reg .u64 t; cvta.to.shared.u64 t, %1; cvt.u32.u64 %0, t; }"
        : "=r"(a) : "l"(p));
    return a;
}
__device__ __forceinline__ void cp_async16(uint32_t smem, const void* g, uint32_t sz) {
    asm volatile("cp.async.cg.shared.global [%0], [%1], 16, %2;"
                 :: "r"(smem), "l"(g), "r"(sz) : "memory");
}
#define CP_COMMIT() asm volatile("cp.async.commit_group;" ::: "memory")
#define CP_WAIT1() asm volatile("cp.async.wait_group 1;" ::: "memory")
#define CP_WAIT0() asm volatile("cp.async.wait_group 0;" ::: "memory")
#define LDSM4(r0, r1, r2, r3, addr) \
    asm volatile("ldmatrix.sync.aligned.m8n8.x4.shared.b16 {%0,%1,%2,%3}, [%4];" \
                 : "=r"(r0), "=r"(r1), "=r"(r2), "=r"(r3) : "r"(addr))
__device__ __forceinline__ void mma16816(float* c, const uint32_t* a, uint32_t b0,
                                         uint32_t b1) {
    asm volatile(
        "mma.sync.aligned.m16n8k16.row.col.f32.f16.f16.f32 "
        "{%0,%1,%2,%3}, {%4,%5,%6,%7}, {%8,%9}, {%0,%1,%2,%3};"
        : "+f"(c[0]), "+f"(c[1]), "+f"(c[2]), "+f"(c[3])
        : "r"(a[0]), "r"(a[1]), "r"(a[2]), "r"(a[3]), "r"(b0), "r"(b1));
}
#define SWZ(x) ((x) ^ (((x) >> 3) & 0x70))

// ============================ scratch (device globals) ============================
__device__ __align__(16) __half g_a1h[12845056];   // conv2 A limbs [pos][ch]
__device__ __align__(16) __half g_a1l[12845056];
__device__ __align__(16) __half g_w2h[1048576];    // conv2 B limbs [n][4096]
__device__ __align__(16) __half g_w2l[1048576];
__device__ __align__(16) __half g_dh[6422528];     // deconv1 A (hi only) [pos][ch]
__device__ __align__(16) __half g_w1h[1638400];    // deconv1 parity weights (hi only)
__device__ float g_w2c[9216];        // deconv2 parity-combined weights [4][9][256]
__device__ float g_h2[3211264];      // pooled conv2 out (atomicMax target)
__device__ float g_encp[1605632];    // encoder split-K partials (98 chunks)
__device__ float g_z[32768];         // rows 0..255 z_e, 256..511 z_q
__device__ __align__(16) __half g_g1h[25690112];   // deconv1 out (fp16)

// ============== fused prep: zero | conv1pool | wsplit2 | wcomb | wcomb2 ===========
// block ranges: [0,3136) zero, [3136,6720) conv1pool, [6720,7744) wsplit2,
//               [7744,14144) wcomb, [14144,14180) wcomb2
__global__ __launch_bounds__(256) void k_prep(const float* __restrict__ x,
                                              const float* __restrict__ w1,
                                              const float* __restrict__ b1,
                                              const float* __restrict__ w2,
                                              const float* __restrict__ d1w,
                                              const float* __restrict__ d2w) {
    __shared__ __align__(16) char sm[4352];
    const int b = blockIdx.x;
    const int t = threadIdx.x;
    if (b < 3136) {
        int i = b * 256 + t;
        if (i < 802816) *(((uint4*)g_h2) + i) = make_uint4(0u, 0u, 0u, 0u);
    } else if (b < 6720) {
        int bb = b - 3136;
        int py = bb % 14;
        int img = bb / 14;
        int c = t;
        float(*xs)[32] = (float(*)[32])sm;
        for (int e = t; e < 5 * 32; e += 256) {
            int r = e / 32, cc = e % 32;
            int iy = 2 * py - 1 + r;
            int ix = cc - 1;
            float v = 0.f;
            if (iy >= 0 && iy < 28 && ix >= 0 && ix < 28)
                v = x[(img * 28 + iy) * 28 + ix];
            xs[r][cc] = v;
        }
        float w[16];
#pragma unroll
        for (int i = 0; i < 16; i++) w[i] = w1[i * 256 + c];
        float bias = b1[c];
        __syncthreads();
        for (int px = 0; px < 14; px++) {
            float mv = -1e30f;
#pragma unroll
            for (int dy = 0; dy < 2; dy++)
#pragma unroll
                for (int dx = 0; dx < 2; dx++) {
                    float v = bias;
#pragma unroll
                    for (int ky = 0; ky < 4; ky++)
#pragma unroll
                        for (int kx = 0; kx < 4; kx++)
                            v += xs[dy + ky][2 * px + dx + kx] * w[ky * 4 + kx];
                    mv = fmaxf(mv, v);
                }
            float val = fmaxf(mv, 0.f);
            int idx = ((img * 14 + py) * 14 + px) * 256 + c;
            __half h = __float2half(val);
            g_a1h[idx] = h;
            g_a1l[idx] = __float2half(val - __half2float(h));
        }
    } else if (b < 7744) {
        int i = b - 6720;
        int k0 = (i & 127) * 32, n0 = (i >> 7) * 32;
        float(*tile)[33] = (float(*)[33])sm;
        int tx = t & 31, ty = t >> 5;
#pragma unroll
        for (int r = 0; r < 32; r += 8)
            tile[ty + r][tx] = w2[(k0 + ty + r) * 256 + n0 + tx];
        __syncthreads();
#pragma unroll
        for (int r = 0; r < 32; r += 8) {
            float v = tile[tx][ty + r];
            int n = n0 + ty + r;
            int idx = n * 4096 + k0 + tx;
            __half h = __float2half(v);
            g_w2h[idx] = h;
            g_w2l[idx] = __float2half(v - __half2float(h));
        }
    } else if (b < 14144) {
        int idx = (b - 7744) * 256 + t;
        int c, base;
        if (idx < 589824) { c = 0; base = 0; }
        else if (idx < 983040) { c = 1; base = 589824; }
        else if (idx < 1376256) { c = 2; base = 983040; }
        else { c = 3; base = 1376256; }
        int py = c >> 1, px = c & 1;
        int TX = 3 - px;
        int Kc = (3 - py) * TX * 256;
        int rem = idx - base;
        int n = rem / Kc;
        int k = rem % Kc;
        int tap = k >> 8, cin = k & 255;
        int ty = tap / TX, tx = tap % TX;
        int kys, kyn, kxs, kxn;
        if (py == 0) { kys = (ty == 0) ? 0 : (ty == 1) ? 1 : 3; kyn = (ty == 1) ? 2 : 1; }
        else { kys = ty * 2; kyn = 2; }
        if (px == 0) { kxs = (tx == 0) ? 0 : (tx == 1) ? 1 : 3; kxn = (tx == 1) ? 2 : 1; }
        else { kxs = tx * 2; kxn = 2; }
        float s = 0.f;
        for (int a = 0; a < kyn; a++)
            for (int bb = 0; bb < kxn; bb++)
                s += d1w[(((kys + a) * 4 + kxs + bb) * 256 + cin) * 256 + n];
        g_w1h[idx] = __float2half(s);
    } else {
        int i = (b - 14144) * 256 + t;
        if (i >= 9216) return;
        int cls = i / 2304;
        int rem = i % 2304;
        int tap = rem >> 8;
        int cin = rem & 255;
        int py = cls >> 1, px = cls & 1;
        int TX = 3 - px, TY = 3 - py;
        if (tap >= TY * TX) { g_w2c[i] = 0.f; return; }
        int ty = tap / TX, tx = tap % TX;
        int kys, kyn, kxs, kxn;
        if (py == 0) { kys = (ty == 0) ? 0 : (ty == 1) ? 1 : 3; kyn = (ty == 1) ? 2 : 1; }
        else { kys = ty * 2; kyn = 2; }
        if (px == 0) { kxs = (tx == 0) ? 0 : (tx == 1) ? 1 : 3; kxn = (tx == 1) ? 2 : 1; }
        else { kxs = tx * 2; kxn = 2; }
        float s = 0.f;
        for (int a = 0; a < kyn; a++)
            for (int bb = 0; bb < kxn; bb++)
                s += d2w[((kys + a) * 4 + kxs + bb) * 256 + cin];
        g_w2c[i] = s;
    }
}

// ============== encoder HMMA implicit-GEMM conv2 (256 threads, R11 config) ========
__global__ __launch_bounds__(256, 1) void k_hmma_enc(
    const __half* __restrict__ a0p, const __half* __restrict__ a1p,
    const __half* __restrict__ b0p, const __half* __restrict__ b1p,
    const float* __restrict__ bias, float* __restrict__ outpool) {
    constexpr int STAGE = 65536;
    extern __shared__ __align__(1024) char smem[];
    const uint32_t sb = smem_to_u32(smem);
    const int t = threadIdx.x;
    const int wid = t >> 5;
    const int lane = t & 31;
    const int wr = wid & 1;
    const int wc = wid >> 1;
    const int m0 = blockIdx.x * 128;
    const int n0 = blockIdx.y * 128;

    const int rr = t >> 3;
    const int seg = t & 7;
    int imgA[4], oyA[4], oxA[4];
    uint32_t stsO[4];
#pragma unroll
    for (int j = 0; j < 4; j++) {
        int m = m0 + rr + 32 * j;
        imgA[j] = m / 196;
        int p = m % 196;
        oyA[j] = p / 14;
        oxA[j] = p % 14;
        stsO[j] = SWZ((uint32_t)((rr + 32 * j) * 128 + seg * 16));
    }

    float acc[4][4][4];
#pragma unroll
    for (int i = 0; i < 4; i++)
#pragma unroll
        for (int j = 0; j < 4; j++)
#pragma unroll
            for (int q = 0; q < 4; q++) acc[i][j][q] = 0.f;

    const int arow = wr * 64 + (lane & 15);
    const uint32_t acolbase = (uint32_t)((lane >> 4) * 16);
    const int brow = wc * 32 + (lane & 7) + (lane >> 4) * 8;
    const uint32_t bcolbase = (uint32_t)(((lane >> 3) & 1) * 16);

    auto issue = [&](int s, int buf) {
        const int tap = s >> 2;
        const int ky = tap >> 2, kx = tap & 3;
        const int ch0 = (s & 3) * 64;
        const uint32_t sbuf = sb + (uint32_t)buf * STAGE;
#pragma unroll
        for (int j = 0; j < 4; j++) {
            int iy = oyA[j] - 1 + ky;
            int ix = oxA[j] - 1 + kx;
            bool v = ((unsigned)iy < 14u) && ((unsigned)ix < 14u);
            int pos = imgA[j] * 196 + iy * 14 + ix;
            int aoff = v ? (pos * 256 + ch0 + seg * 8) : 0;
            uint32_t sz = v ? 16u : 0u;
            cp_async16(sbuf + stsO[j], a0p + aoff, sz);
            cp_async16(sbuf + 16384 + stsO[j], a1p + aoff, sz);
            size_t boff = (size_t)(n0 + rr + 32 * j) * 4096 + s * 64 + seg * 8;
            cp_async16(sbuf + 32768 + stsO[j], b0p + boff, 16u);
            cp_async16(sbuf + 49152 + stsO[j], b1p + boff, 16u);
        }
    };

    uint32_t af[2][2][4][4];
    uint32_t bf[2][2][2][4];
    auto ldfrag = [&](uint32_t abase, uint32_t bbase, int slot, int kk) {
        const uint32_t acol = acolbase + kk * 32;
#pragma unroll
        for (int la = 0; la < 2; la++)
#pragma unroll
            for (int mt = 0; mt < 4; mt++) {
                int row = arow + mt * 16;
                LDSM4(af[slot][la][mt][0], af[slot][la][mt][1], af[slot][la][mt][2],
                      af[slot][la][mt][3],
                      abase + la * 16384 + row * 128 + (acol ^ ((row & 7) * 16)));
            }
        const uint32_t bcol = bcolbase + kk * 32;
#pragma unroll
        for (int lb = 0; lb < 2; lb++)
#pragma unroll
            for (int nt2 = 0; nt2 < 2; nt2++) {
                int row = brow + nt2 * 16;
                LDSM4(bf[slot][lb][nt2][0], bf[slot][lb][nt2][1], bf[slot][lb][nt2][2],
                      bf[slot][lb][nt2][3],
                      bbase + lb * 16384 + row * 128 + (bcol ^ ((row & 7) * 16)));
            }
    };

    issue(0, 0);
    CP_COMMIT();
    issue(1, 1);
    CP_COMMIT();

    int buf = 0;
    for (int s = 0; s < 64; s++) {
        if (s + 1 < 64) CP_WAIT1(); else CP_WAIT0();
        __syncthreads();
        if (s + 2 < 64) {
            int nb = buf + 2;
            if (nb >= 3) nb -= 3;
            issue(s + 2, nb);
            CP_COMMIT();
        }
        const uint32_t abase = sb + (uint32_t)buf * STAGE;
        const uint32_t bbase = abase + 32768;
        ldfrag(abase, bbase, 0, 0);
#pragma unroll
        for (int kk = 0; kk < 4; kk++) {
            const int cur = kk & 1;
            if (kk < 3) ldfrag(abase, bbase, cur ^ 1, kk + 1);
#pragma unroll
            for (int p = 0; p < 3; p++) {
                const int la = (p == 2) ? 1 : 0;
                const int lb = (p == 1) ? 1 : 0;
#pragma unroll
                for (int mt = 0; mt < 4; mt++)
#pragma unroll
                    for (int nt = 0; nt < 4; nt++)
                        mma16816(acc[mt][nt], af[cur][la][mt],
                                 bf[cur][lb][nt >> 1][(nt & 1) * 2],
                                 bf[cur][lb][nt >> 1][(nt & 1) * 2 + 1]);
            }
        }
        if (++buf == 3) buf = 0;
    }

    unsigned* outp = (unsigned*)outpool;
#pragma unroll
    for (int mt = 0; mt < 4; mt++) {
#pragma unroll
        for (int nt = 0; nt < 4; nt++) {
            int col = n0 + wc * 32 + nt * 8 + (lane & 3) * 2;
            float b0v = bias[col], b1v = bias[col + 1];
#pragma unroll
            for (int h8 = 0; h8 < 2; h8++) {
                int m = m0 + wr * 64 + mt * 16 + (lane >> 2) + h8 * 8;
                int img = m / 196;
                int p = m % 196;
                int py = (p / 14) >> 1;
                int px = (p % 14) >> 1;
                size_t base = (size_t)((img * 7 + py) * 7 + px) * 256 + col;
                float v0 = fmaxf(acc[mt][nt][h8 * 2] + b0v, 0.f);
                float v1 = fmaxf(acc[mt][nt][h8 * 2 + 1] + b1v, 0.f);
                atomicMax(outp + base, __float_as_uint(v0));
                atomicMax(outp + base + 1, __float_as_uint(v1));
            }
        }
    }
}

// ============== decoder HMMA (R11 config): parity, single-limb, fp16 out ==========
__global__ __launch_bounds__(256, 1) void k_hmma_dec(
    const __half* __restrict__ a0p, const __half* __restrict__ b0p,
    const float* __restrict__ bias, __half* __restrict__ out) {
    constexpr int STAGE = 32768;
    extern __shared__ __align__(1024) char smem[];
    const uint32_t sb = smem_to_u32(smem);
    const int t = threadIdx.x;
    const int wid = t >> 5;
    const int lane = t & 31;
    const int wr = wid & 1;
    const int wc = wid >> 1;
    const int m0 = blockIdx.x * 128;
    const int n0 = blockIdx.y * 128;
    const int cls = blockIdx.z;
    const int py = cls >> 1, px = cls & 1;
    const int TX = 3 - px;
    const int TY = 3 - py;
    const int nst = TY * TX * 4;
    const int Kc = TY * TX * 256;
    const int woff = (cls == 0) ? 0 : (cls == 1) ? 589824 : (cls == 2) ? 983040
                                                                       : 1376256;

    const int rr = t >> 3;
    const int seg = t & 7;
    int imgA[4], syA[4], sxA[4];
    uint32_t stsO[4];
#pragma unroll
    for (int j = 0; j < 4; j++) {
        int m = m0 + rr + 32 * j;
        imgA[j] = m / 49;
        int p = m % 49;
        syA[j] = p / 7;
        sxA[j] = p % 7;
        stsO[j] = SWZ((uint32_t)((rr + 32 * j) * 128 + seg * 16));
    }

    float acc[4][4][4];
#pragma unroll
    for (int i = 0; i < 4; i++)
#pragma unroll
        for (int j = 0; j < 4; j++)
#pragma unroll
            for (int q = 0; q < 4; q++) acc[i][j][q] = 0.f;

    const int arow = wr * 64 + (lane & 15);
    const uint32_t acolbase = (uint32_t)((lane >> 4) * 16);
    const int brow = wc * 32 + (lane & 7) + (lane >> 4) * 8;
    const uint32_t bcolbase = (uint32_t)(((lane >> 3) & 1) * 16);

    auto issue = [&](int s, int buf) {
        const int tap = s >> 2;
        const int ch0 = (s & 3) * 64;
        const int ty = tap / TX, tx = tap % TX;
        const uint32_t sbuf = sb + (uint32_t)buf * STAGE;
#pragma unroll
        for (int j = 0; j < 4; j++) {
            int iy = syA[j] + ty + (py - 1);
            int ix = sxA[j] + tx + (px - 1);
            bool v = ((unsigned)iy < 7u) && ((unsigned)ix < 7u);
            int pos = imgA[j] * 49 + iy * 7 + ix;
            int aoff = v ? (pos * 256 + ch0 + seg * 8) : 0;
            uint32_t sz = v ? 16u : 0u;
            cp_async16(sbuf + stsO[j], a0p + aoff, sz);
            size_t boff = (size_t)woff + (size_t)(n0 + rr + 32 * j) * Kc + s * 64 +
                          seg * 8;
            cp_async16(sbuf + 16384 + stsO[j], b0p + boff, 16u);
        }
    };

    uint32_t af[2][4][4];
    uint32_t bf[2][2][4];
    auto ldfrag = [&](uint32_t abase, uint32_t bbase, int slot, int kk) {
        const uint32_t acol = acolbase + kk * 32;
#pragma unroll
        for (int mt = 0; mt < 4; mt++) {
            int row = arow + mt * 16;
            LDSM4(af[slot][mt][0], af[slot][mt][1], af[slot][mt][2], af[slot][mt][3],
                  abase + row * 128 + (acol ^ ((row & 7) * 16)));
        }
        const uint32_t bcol = bcolbase + kk * 32;
#pragma unroll
        for (int nt2 = 0; nt2 < 2; nt2++) {
            int row = brow + nt2 * 16;
            LDSM4(bf[slot][nt2][0], bf[slot][nt2][1], bf[slot][nt2][2],
                  bf[slot][nt2][3],
                  bbase + row * 128 + (bcol ^ ((row & 7) * 16)));
        }
    };

    issue(0, 0);
    CP_COMMIT();
    issue(1, 1);
    CP_COMMIT();

    int buf = 0;
    for (int s = 0; s < nst; s++) {
        if (s + 1 < nst) CP_WAIT1(); else CP_WAIT0();
        __syncthreads();
        if (s + 2 < nst) {
            int nb = buf + 2;
            if (nb >= 3) nb -= 3;
            issue(s + 2, nb);
            CP_COMMIT();
        }
        const uint32_t abase = sb + (uint32_t)buf * STAGE;
        const uint32_t bbase = abase + 16384;
        ldfrag(abase, bbase, 0, 0);
#pragma unroll
        for (int kk = 0; kk < 4; kk++) {
            const int cur = kk & 1;
            if (kk < 3) ldfrag(abase, bbase, cur ^ 1, kk + 1);
#pragma unroll
            for (int mt = 0; mt < 4; mt++)
#pragma unroll
                for (int nt = 0; nt < 4; nt++)
                    mma16816(acc[mt][nt], af[cur][mt],
                             bf[cur][nt >> 1][(nt & 1) * 2],
                             bf[cur][nt >> 1][(nt & 1) * 2 + 1]);
        }
        if (++buf == 3) buf = 0;
    }

#pragma unroll
    for (int mt = 0; mt < 4; mt++) {
#pragma unroll
        for (int nt = 0; nt < 4; nt++) {
            int col = n0 + wc * 32 + nt * 8 + (lane & 3) * 2;
            float b0v = bias[col], b1v = bias[col + 1];
#pragma unroll
            for (int half8 = 0; half8 < 2; half8++) {
                int m = m0 + wr * 64 + mt * 16 + (lane >> 2) + half8 * 8;
                int img = m / 49;
                int p = m % 49;
                int oy = 2 * (p / 7) + py;
                int ox = 2 * (p % 7) + px;
                float v0 = fmaxf(acc[mt][nt][half8 * 2] + b0v, 0.f);
                float v1 = fmaxf(acc[mt][nt][half8 * 2 + 1] + b1v, 0.f);
                __half2 hv = __floats2half2_rn(v0, v1);
                *(__half2*)(out + (size_t)((img * 14 + oy) * 14 + ox) * 256 + col) = hv;
            }
        }
    }
}

// ---------------- K4: encoder FC split-K (98 chunks of K=128) ----------------
__global__ __launch_bounds__(256) void k_enc_part(const float* __restrict__ h2,
                                                  const float* __restrict__ ew) {
    int kc = blockIdx.x;
    int b0 = blockIdx.y * 64;
    __shared__ float As[8][64];
    __shared__ float Bs[8][64];
    int t = threadIdx.x;
    int abb = t >> 2, akk = (t & 3) * 2;
    int bkk = t >> 5, bll = (t & 31) * 2;
    int tr = t >> 4, tc = t & 15;
    float acc[4][4] = {};
    int kbase = kc * 128;
    for (int ks = 0; ks < 128; ks += 8) {
        int k0 = kbase + ks;
        float2 av = *(const float2*)&h2[(b0 + abb) * 12544 + k0 + akk];
        float2 bv = *(const float2*)&ew[(k0 + bkk) * 64 + bll];
        __syncthreads();
        As[akk][abb] = av.x;
        As[akk + 1][abb] = av.y;
        *(float2*)&Bs[bkk][bll] = bv;
        __syncthreads();
#pragma unroll
        for (int kk = 0; kk < 8; kk++) {
            float a[4], b[4];
#pragma unroll
            for (int i = 0; i < 4; i++) a[i] = As[kk][tr * 4 + i];
#pragma unroll
            for (int j = 0; j < 4; j++) b[j] = Bs[kk][tc * 4 + j];
#pragma unroll
            for (int i = 0; i < 4; i++)
#pragma unroll
                for (int j = 0; j < 4; j++) acc[i][j] += a[i] * b[j];
        }
    }
#pragma unroll
    for (int i = 0; i < 4; i++)
#pragma unroll
        for (int j = 0; j < 4; j++)
            g_encp[(kc * 256 + b0 + tr * 4 + i) * 64 + tc * 4 + j] = acc[i][j];
}

// ---- K5: fused parallel reduce + argmin (float4 distance loop) + z_q gather ----
__global__ __launch_bounds__(256) void k_redargmin(const float* __restrict__ emb,
                                                   const float* __restrict__ eb) {
    int b = blockIdx.x;
    __shared__ float ps[4][64];
    __shared__ __align__(16) float zb[64];
    __shared__ float ds[256];
    __shared__ int ki[256];
    int t = threadIdx.x;
    {
        int lat = t & 63;
        int g = t >> 6;
        float s = 0.f;
        for (int kc = g; kc < 98; kc += 4) s += g_encp[kc * 16384 + b * 64 + lat];
        ps[g][lat] = s;
    }
    __syncthreads();
    if (t < 64) {
        float z = eb[t] + ((ps[0][t] + ps[1][t]) + (ps[2][t] + ps[3][t]));
        zb[t] = z;
        g_z[b * 64 + t] = z;
    }
    __syncthreads();
    // distance: float4 loads, scalar-order accumulation (bitwise-identical)
    float d = 0.f;
    const float4* e4 = (const float4*)(emb + t * 64);
    const float4* z4 = (const float4*)zb;
#pragma unroll
    for (int j = 0; j < 16; j++) {
        float4 ev = e4[j];
        float4 zv = z4[j];
        float df;
        df = zv.x - ev.x; d += df * df;
        df = zv.y - ev.y; d += df * df;
        df = zv.z - ev.z; d += df * df;
        df = zv.w - ev.w; d += df * df;
    }
    ds[t] = d;
    ki[t] = t;
    __syncthreads();
    for (int s = 128; s > 0; s >>= 1) {
        if (t < s) {
            float d2 = ds[t + s];
            int k2 = ki[t + s];
            if (d2 < ds[t] || (d2 == ds[t] && k2 < ki[t])) { ds[t] = d2; ki[t] = k2; }
        }
        __syncthreads();
    }
    int kb = ki[0];
    if (t < 64) g_z[(256 + b) * 64 + t] = emb[kb * 64 + t];
}

// ---------------- K6: decoder FC -> fp16 hi plane only ----------------
__global__ __launch_bounds__(256) void k_decfc(const float* __restrict__ dw,
                                               const float* __restrict__ db) {
    int n0 = blockIdx.x * 128;
    int m0 = blockIdx.y * 64;
    __shared__ float Zs[64][64];
    __shared__ float Bs[32][128];
    int t = threadIdx.x;
    {
        int rr = t >> 2, kk0 = (t & 3) * 16;
        const float* zp = &g_z[(m0 + rr) * 64 + kk0];
#pragma unroll
        for (int q = 0; q < 4; q++) {
            float4 v = *(const float4*)(zp + q * 4);
            Zs[kk0 + q * 4 + 0][rr] = v.x; Zs[kk0 + q * 4 + 1][rr] = v.y;
            Zs[kk0 + q * 4 + 2][rr] = v.z; Zs[kk0 + q * 4 + 3][rr] = v.w;
        }
    }
    int tr = t >> 5;
    int tc = t & 31;
    float acc[8][4] = {};
    for (int khf = 0; khf < 2; khf++) {
        __syncthreads();
        {
            int nn = (t & 31) * 4;
            int kk = t >> 5;
#pragma unroll
            for (int q = 0; q < 4; q++) {
                int row = kk + q * 8;
                *(float4*)&Bs[row][nn] =
                    *(const float4*)&dw[(khf * 32 + row) * 12544 + n0 + nn];
            }
        }
        __syncthreads();
#pragma unroll
        for (int kk = 0; kk < 32; kk++) {
            int kg = khf * 32 + kk;
            float a[8];
#pragma unroll
            for (int i = 0; i < 8; i++) a[i] = Zs[kg][tr * 8 + i];
            float4 b4 = *(const float4*)&Bs[kk][tc * 4];
            float bb[4] = {b4.x, b4.y, b4.z, b4.w};
#pragma unroll
            for (int i = 0; i < 8; i++)
#pragma unroll
                for (int j = 0; j < 4; j++) acc[i][j] += a[i] * bb[j];
        }
    }
#pragma unroll
    for (int i = 0; i < 8; i++) {
        int m = m0 + tr * 8 + i;
#pragma unroll
        for (int j = 0; j < 4; j++) {
            int f = n0 + tc * 4 + j;
            float v = acc[i][j] + db[f];
            g_dh[(size_t)m * 12544 + f] = __float2half(v);
        }
    }
}

// ---------------- K8: deconv2 single-pass (fp16 image, full-channel lanes) --------
__global__ __launch_bounds__(256) void k_deconv2p(const float* __restrict__ b2,
                                                  float* __restrict__ out) {
    extern __shared__ __align__(16) char dsm[];
    __half* gsm = (__half*)dsm;
    float* wsm = (float*)(dsm + 57344);
    int img = blockIdx.x;
    int half = blockIdx.y;
    int y0 = half * 14;
    int gbase = half * 6;
    int t = threadIdx.x;
    int wrp = t >> 5, lane = t & 31;
    float bias = b2[0];

    {
        const uint4* src =
            (const uint4*)(g_g1h + (size_t)(img * 196 + gbase * 14) * 256);
        uint4* dst = (uint4*)gsm;
        for (int e = t; e < 3584; e += 256) dst[e] = src[e];
    }
    {
        const float4* src = (const float4*)g_w2c;
        float4* dst = (float4*)wsm;
        for (int e = t; e < 2304; e += 256) dst[e] = src[e];
    }
    __syncthreads();

    for (int p = wrp; p < 392; p += 8) {
        int yy = p / 28, x = p % 28;
        int y = y0 + yy;
        int py = y & 1, px = x & 1;
        int cls = py * 2 + px;
        int sy = y >> 1, sx = x >> 1;
        int TY = 3 - py, TX = 3 - px;
        float r = 0.f;
        for (int ty = 0; ty < TY; ty++) {
            int iy = sy + ty + py - 1;
            if ((unsigned)iy >= 14u) continue;
            int gy = iy - gbase;
            for (int tx = 0; tx < TX; tx++) {
                int ix = sx + tx + px - 1;
                if ((unsigned)ix >= 14u) continue;
                const __half2* gp =
                    (const __half2*)(gsm + (gy * 14 + ix) * 256 + lane * 8);
                const float* wp = wsm + (cls * 9 + ty * TX + tx) * 256 + lane * 8;
#pragma unroll
                for (int q = 0; q < 4; q++) {
                    float2 g2 = __half22float2(gp[q]);
                    r += g2.x * wp[2 * q] + g2.y * wp[2 * q + 1];
                }
            }
        }
#pragma unroll
        for (int s = 16; s > 0; s >>= 1) r += __shfl_xor_sync(0xffffffffu, r, s);
        if (lane == 0) {
            float v = r + bias;
            out[img * 784 + y * 28 + x] = 1.f / (1.f + expf(-v));
        }
    }
}

// ---------------- launch ----------------
static constexpr int SMEM_ENC = 3 * 65536;
static constexpr int SMEM_DEC = 3 * 32768;
static constexpr int SMEM_D2 = 57344 + 36864;

extern "C" void kernel_launch(void* const* d_in, const int* in_sizes, int n_in,
                              void* d_out, int out_size) {
    const float* x   = (const float*)d_in[0];
    const float* c1w = (const float*)d_in[1];
    const float* c1b = (const float*)d_in[2];
    const float* c2w = (const float*)d_in[3];
    const float* c2b = (const float*)d_in[4];
    const float* ew  = (const float*)d_in[5];
    const float* eb  = (const float*)d_in[6];
    const float* emb = (const float*)d_in[7];
    const float* dw  = (const float*)d_in[8];
    const float* db  = (const float*)d_in[9];
    const float* d1w = (const float*)d_in[10];
    const float* d1b = (const float*)d_in[11];
    const float* d2w = (const float*)d_in[12];
    const float* d2b = (const float*)d_in[13];
    float* out = (float*)d_out;

    void *pa1h, *pa1l, *pw2h, *pw2l, *pdh, *pw1h, *ph2, *pg1;
    cudaGetSymbolAddress(&pa1h, g_a1h);
    cudaGetSymbolAddress(&pa1l, g_a1l);
    cudaGetSymbolAddress(&pw2h, g_w2h);
    cudaGetSymbolAddress(&pw2l, g_w2l);
    cudaGetSymbolAddress(&pdh, g_dh);
    cudaGetSymbolAddress(&pw1h, g_w1h);
    cudaGetSymbolAddress(&ph2, g_h2);
    cudaGetSymbolAddress(&pg1, g_g1h);

    cudaFuncSetAttribute((const void*)k_hmma_enc,
                         cudaFuncAttributeMaxDynamicSharedMemorySize, SMEM_ENC);
    cudaFuncSetAttribute((const void*)k_hmma_dec,
                         cudaFuncAttributeMaxDynamicSharedMemorySize, SMEM_DEC);
    cudaFuncSetAttribute((const void*)k_deconv2p,
                         cudaFuncAttributeMaxDynamicSharedMemorySize, SMEM_D2);

    k_prep<<<14180, 256>>>(x, c1w, c1b, c2w, d1w, d2w);
    k_hmma_enc<<<dim3(392, 2), 256, SMEM_ENC>>>(
        (const __half*)pa1h, (const __half*)pa1l, (const __half*)pw2h,
        (const __half*)pw2l, c2b, (float*)ph2);
    k_enc_part<<<dim3(98, 4), 256>>>((const float*)ph2, ew);
    k_redargmin<<<256, 256>>>(emb, eb);
    k_decfc<<<dim3(98, 8), 256>>>(dw, db);
    k_hmma_dec<<<dim3(196, 2, 4), 256, SMEM_DEC>>>(
        (const __half*)pdh, (const __half*)pw1h, d1b, (__half*)pg1);
    k_deconv2p<<<dim3(512, 2), 256, SMEM_D2>>>(d2b, out);
}